// round 16
// baseline (speedup 1.0000x reference)
#include <cuda_runtime.h>
#include <cuda_fp16.h>
#include <cstdint>

#define Bb 2
#define Ss 4096
#define Dd 768
#define Hh 12
#define DHd 64
#define Ww 128
#define Gg 16
#define NBb 32
#define NSPLIT 32
#define NEGF (-1.0e9f)

// ---------------- scratch (device globals; no allocation) ----------------
__device__ float g_kg[Bb*Hh*Ss*DHd];
__device__ float g_vg[Bb*Hh*Ss*DHd];
__device__ float g_qg[Bb*Hh*Gg*DHd];
__device__ float g_pm  [Bb*Hh*NSPLIT*Gg];
__device__ float g_pl  [Bb*Hh*NSPLIT*Gg];
__device__ float g_pacc[Bb*Hh*NSPLIT*Gg*DHd];

__device__ __half g_x  [Bb*Ss*Dd];
__device__ __half g_a  [Bb*Ss*Dd];
__device__ __half g_wt [6*Dd*Dd];
__device__ __half g_qf [Bb*Hh*Ss*DHd];
__device__ __half g_kf [Bb*Hh*Ss*DHd];
__device__ __half g_vf [Bb*Hh*Ss*DHd];

struct W6   { const float* w[6]; };
struct Bia5 { const float* b[5]; };

// ================= warp-MMA helpers =================
#define SWZ(o) ((o) ^ (((o) >> 3) & 0x70))

__device__ __forceinline__ uint32_t smem_u32(const void* p) {
    uint32_t a;
    asm("{ .reg .u64 t; cvta.to.shared.u64 t, %1; cvt.u32.u64 %0, t; }" : "=r"(a) : "l"(p));
    return a;
}
__device__ __forceinline__ void ldsm4(uint32_t* r, uint32_t addr) {
    asm volatile("ldmatrix.sync.aligned.m8n8.x4.shared.b16 {%0,%1,%2,%3}, [%4];"
                 : "=r"(r[0]), "=r"(r[1]), "=r"(r[2]), "=r"(r[3]) : "r"(addr));
}
__device__ __forceinline__ void ldsm4t(uint32_t* r, uint32_t addr) {
    asm volatile("ldmatrix.sync.aligned.m8n8.x4.trans.shared.b16 {%0,%1,%2,%3}, [%4];"
                 : "=r"(r[0]), "=r"(r[1]), "=r"(r[2]), "=r"(r[3]) : "r"(addr));
}
__device__ __forceinline__ void mma16816(float* d, const uint32_t* a, uint32_t b0, uint32_t b1) {
    asm volatile(
        "mma.sync.aligned.m16n8k16.row.col.f32.f16.f16.f32 "
        "{%0,%1,%2,%3}, {%4,%5,%6,%7}, {%8,%9}, {%0,%1,%2,%3};"
        : "+f"(d[0]), "+f"(d[1]), "+f"(d[2]), "+f"(d[3])
        : "r"(a[0]), "r"(a[1]), "r"(a[2]), "r"(a[3]), "r"(b0), "r"(b1));
}
__device__ __forceinline__ uint32_t pack_h2(float e0, float e1) {
    __half2 h = __floats2half2_rn(e0, e1);
    return *(uint32_t*)&h;
}
__device__ __forceinline__ void cpasync16(uint32_t dst, const void* src) {
    asm volatile("cp.async.cg.shared.global [%0], [%1], 16;" :: "r"(dst), "l"(src) : "memory");
}

// ================= prep kernels =================
__global__ __launch_bounds__(256) void to_f16(const float* __restrict__ in,
                                              __half* __restrict__ out16, int n4)
{
    int i = blockIdx.x * 256 + threadIdx.x;
    if (i >= n4) return;
    float4 v = ((const float4*)in)[i];
    union { __half h[4]; uint2 u; } uh;
    uh.h[0] = __float2half_rn(v.x);
    uh.h[1] = __float2half_rn(v.y);
    uh.h[2] = __float2half_rn(v.z);
    uh.h[3] = __float2half_rn(v.w);
    *(uint2*)(out16 + (size_t)i * 4) = uh.u;
}

__global__ __launch_bounds__(256) void prep_w(W6 ws)
{
    __shared__ float t[32][33];
    int z = blockIdx.z;
    const float* W = ws.w[z];
    __half* oh = g_wt + (size_t)z * Dd * Dd;
    int k0 = blockIdx.x * 32, n0 = blockIdx.y * 32;
    int tx = threadIdx.x, ty = threadIdx.y;
#pragma unroll
    for (int r = 0; r < 4; r++)
        t[ty + r * 8][tx] = W[(size_t)(k0 + ty + r * 8) * Dd + n0 + tx];
    __syncthreads();
#pragma unroll
    for (int r = 0; r < 4; r++)
        oh[(size_t)(n0 + ty + r * 8) * Dd + k0 + tx] = __float2half_rn(t[tx][ty + r * 8]);
}

// ===== fp16 GEMM v5: BM64 x BN256, BK=64, 256 thr, 2 CTAs/SM, 2-stage =====
// stage: A 8K | B 32K = 40K
#define STAGE_SZ 40960
#define GEMM_SMEM (2 * STAGE_SZ)

template<bool OUT>
__global__ __launch_bounds__(256, 2)
void mma_gemm(const __half* __restrict__ Af,
              Bia5 bp, const float* __restrict__ bias_o, float* __restrict__ outp)
{
    extern __shared__ char smem[];
    uint32_t sb = smem_u32(smem);
    int tid = threadIdx.x;
    int wid = tid >> 5, lane = tid & 31;
    int wm = wid >> 2, wn = wid & 3;          // 2m x 4n warps; warp tile 32m x 64n
    int z = OUT ? 5 : blockIdx.z;
    int n0 = blockIdx.x * 256, m0 = blockIdx.y * 64;

    const __half* Bw = g_wt + (size_t)z * Dd * Dd + (size_t)n0 * Dd;
    const __half* Ah = Af + (size_t)m0 * Dd;

    float acc[2][8][4];
#pragma unroll
    for (int i = 0; i < 2; i++)
#pragma unroll
        for (int j = 0; j < 8; j++)
#pragma unroll
            for (int q = 0; q < 4; q++) acc[i][j][q] = 0.f;

    int alr = lane & 15, alc = lane >> 4, arx = lane & 7;
    uint32_t aoff[2];
#pragma unroll
    for (int mi = 0; mi < 2; mi++) aoff[mi] = (wm * 32 + mi * 16 + alr) * 128;
    int blr = (lane & 7) + ((lane >> 4) & 1) * 8;
    int blc = (lane >> 3) & 1, brx = lane & 7;
    uint32_t boff[4];
#pragma unroll
    for (int ni = 0; ni < 4; ni++) boff[ni] = (wn * 64 + ni * 16 + blr) * 128;

    // loader: 2560 x 16B units per stage (A 512, B 2048), 256 thr -> 10 each
    auto load_stage = [&](int c, int s) {
        int k0 = c * 64;
        uint32_t base = sb + s * STAGE_SZ;
#pragma unroll
        for (int it = 0; it < 10; it++) {
            int idx = tid + it * 256;
            int cu = idx & 7;
            if (idx < 512) {               // A: 64 rows
                int row = idx >> 3;
                cpasync16(base + SWZ(row * 128 + cu * 16),
                          Ah + k0 + (size_t)row * Dd + cu * 8);
            } else {                       // B: 256 rows
                int row = (idx - 512) >> 3;
                cpasync16(base + 8192 + SWZ(row * 128 + cu * 16),
                          Bw + k0 + (size_t)row * Dd + cu * 8);
            }
        }
    };

    load_stage(0, 0);
    asm volatile("cp.async.commit_group;" ::: "memory");

    for (int c = 0; c < 12; c++) {
        asm volatile("cp.async.wait_group 0;" ::: "memory");
        __syncthreads();
        if (c < 11) {
            load_stage(c + 1, (c + 1) & 1);
            asm volatile("cp.async.commit_group;" ::: "memory");
        }
        uint32_t sA = sb + (c & 1) * STAGE_SZ;
        uint32_t sB = sA + 8192;
#pragma unroll
        for (int ks = 0; ks < 4; ks++) {
            uint32_t ah[2][4], bh[4][4];
            uint32_t ac = ((uint32_t)(ks * 2 + alc) ^ arx) << 4;
            uint32_t bc = ((uint32_t)(ks * 2 + blc) ^ brx) << 4;
#pragma unroll
            for (int mi = 0; mi < 2; mi++) ldsm4(ah[mi], sA + aoff[mi] + ac);
#pragma unroll
            for (int ni = 0; ni < 4; ni++) ldsm4(bh[ni], sB + boff[ni] + bc);
#pragma unroll
            for (int mi = 0; mi < 2; mi++)
#pragma unroll
                for (int nj = 0; nj < 8; nj++) {
                    int ni = nj >> 1, hf = (nj & 1) * 2;
                    mma16816(acc[mi][nj], ah[mi], bh[ni][hf], bh[ni][hf + 1]);
                }
        }
    }

    int g = lane >> 2, t4 = lane & 3;
#pragma unroll
    for (int mi = 0; mi < 2; mi++) {
        int r0 = m0 + wm * 32 + mi * 16 + g;
#pragma unroll
        for (int nj = 0; nj < 8; nj++) {
            int cc = n0 + wn * 64 + nj * 8 + t4 * 2;
#pragma unroll
            for (int half = 0; half < 2; half++) {
                int m = r0 + half * 8;
                float v0 = acc[mi][nj][half * 2 + 0];
                float v1 = acc[mi][nj][half * 2 + 1];
                if (OUT) {
                    float2 o = make_float2(v0 + bias_o[cc], v1 + bias_o[cc + 1]);
                    *(float2*)(outp + (size_t)m * Dd + cc) = o;
                } else {
                    const float* bias = bp.b[z];
                    float scale = (z == 0) ? 0.125f : 1.0f;
                    v0 = (v0 + bias[cc]) * scale;
                    v1 = (v1 + bias[cc + 1]) * scale;
                    int b = m >> 12, s = m & 4095;
                    int h = cc >> 6, d0 = cc & 63;
                    size_t base = (((size_t)(b * Hh + h)) * Ss + s) * DHd + d0;
                    if (z >= 3) {
                        float* dstz = (z == 3) ? g_kg : g_vg;
                        *(float2*)(dstz + base) = make_float2(v0, v1);
                    } else {
                        __half* dst = (z == 0) ? g_qf : ((z == 1) ? g_kf : g_vf);
                        *(uint32_t*)(dst + base) = pack_h2(v0, v1);
                    }
                }
            }
        }
    }
}

// ===== local attention: 64-query CTAs, band-aware chunk skipping =====
#define LA_KOK   0
#define LA_Q     1024
#define LA_K     (LA_Q + 8192)
#define LA_V     (LA_K + 16384)
#define LA_SMEM  (LA_V + 16384)

__global__ __launch_bounds__(128, 3) void local_attn(const int* __restrict__ mask)
{
    extern __shared__ char smem[];
    uint32_t sb = smem_u32(smem);
    float* kok = (float*)(smem + LA_KOK);

    int nh = blockIdx.x, h = blockIdx.y, b = blockIdx.z;
    int n = nh >> 1, half64 = nh & 1;
    int tid = threadIdx.x;
    int wid = tid >> 5, lane = tid & 31;
    int g = lane >> 2, t4 = lane & 3;
    int qr = wid * 16;
    int qbase = n * Ww + half64 * 64;

    size_t bhbase = ((size_t)(b * Hh + h)) * Ss * DHd;
    const __half* q_g = g_qf + bhbase + (size_t)qbase * DHd;
    const __half* k_g = g_kf + bhbase;
    const __half* v_g = g_vf + bhbase;
    const int* mk = mask + b * Ss;

#pragma unroll
    for (int it = 0; it < 4; it++) {
        int idx = tid + it * 128;
        int row = idx >> 3, cu = idx & 7;
        uint32_t sw = row * 128 + ((cu ^ (row & 7)) << 4);
        *(uint4*)(smem + LA_Q + sw) = *(const uint4*)(q_g + (size_t)row * DHd + cu * 8);
    }

    float sacc[16][4];
    float O[8][4];
#pragma unroll
    for (int j = 0; j < 8; j++)
#pragma unroll
        for (int q = 0; q < 4; q++) O[j][q] = 0.f;
    float m0 = -3.0e38f, m1 = -3.0e38f, l0 = 0.f, l1 = 0.f;

    uint32_t aboff = (qr + (lane & 15)) * 128;
    int arx = lane & 7;
    int alc = lane >> 4;
    int krow_in = (lane & 7) + 8 * ((lane >> 4) & 1);
    int kcc = (lane >> 3) & 1;
    int tkrow = (lane & 7) + 8 * ((lane >> 3) & 1);
    int tdu = lane >> 4;

    for (int c = 0; c < 4; c++) {
        int p0 = (n - 1) * Ww + c * Ww;
        // band-aware 16-col group range [jlo, jhi): bit-exact skips
        int jlo = 0, jhi = 8;
        if (c == 3) jhi = 1;                          // global cols: only keys 0-15
        else if (c == 0 && half64 == 1) jlo = 4;      // rel >= -128 => col >= 64
        else if (c == 2 && half64 == 0) jhi = 4;      // rel <= 128 => col <= 63

        __syncthreads();
        {
            bool ok;
            if (c == 3) ok = (tid < Gg) && (mk[tid] > 0);
            else { int p = p0 + tid; ok = (p >= Gg) && (p < Ss) && (mk[p] > 0); }
            kok[tid] = ok ? 1.f : 0.f;
        }
#pragma unroll
        for (int it = 0; it < 8; it++) {
            int idx = tid + it * 128;
            int j = idx >> 3, cu = idx & 7;
            int p = (c == 3) ? j : (p0 + j);
            bool inr = (c == 3) ? (j < Gg) : (p >= 0 && p < Ss);
            uint4 kv = make_uint4(0, 0, 0, 0), vv = make_uint4(0, 0, 0, 0);
            if (inr) {
                size_t gb = (size_t)p * DHd + cu * 8;
                kv = *(const uint4*)(k_g + gb);
                vv = *(const uint4*)(v_g + gb);
            }
            uint32_t sw = j * 128 + ((cu ^ (j & 7)) << 4);
            *(uint4*)(smem + LA_K + sw) = kv;
            *(uint4*)(smem + LA_V + sw) = vv;
        }
        __syncthreads();

        // ---- S = Q.K^T over [jlo, jhi) groups ----
#pragma unroll
        for (int j = 0; j < 16; j++)
#pragma unroll
            for (int q = 0; q < 4; q++) sacc[j][q] = 0.f;
#pragma unroll
        for (int ks = 0; ks < 4; ks++) {
            uint32_t qh4[4];
            uint32_t ac = ((uint32_t)(ks * 2 + alc) ^ arx) << 4;
            ldsm4(qh4, sb + LA_Q + aboff + ac);
#pragma unroll
            for (int jj = 0; jj < 8; jj++) {
                if (jj < jlo || jj >= jhi) continue;
                uint32_t kh4[4];
                uint32_t kb = (16 * jj + krow_in) * 128 + (((uint32_t)(ks * 2 + kcc) ^ arx) << 4);
                ldsm4(kh4, sb + LA_K + kb);
                mma16816(sacc[2 * jj],     qh4, kh4[0], kh4[1]);
                mma16816(sacc[2 * jj + 1], qh4, kh4[2], kh4[3]);
            }
        }

        // ---- mask (in-range groups only) ----
        int row0 = qbase + qr + g;
        int row1 = row0 + 8;
#pragma unroll
        for (int j = 0; j < 16; j++) {
            if (j < 2 * jlo || j >= 2 * jhi) continue;
#pragma unroll
            for (int q = 0; q < 4; q++) {
                int col = 8 * j + t4 * 2 + (q & 1);
                int row = (q >= 2) ? row1 : row0;
                bool ok = kok[col] > 0.f;
                if (c != 3) {
                    int rel = (p0 + col) - row;
                    ok = ok && (rel <= Ww) && (rel >= -Ww);
                }
                if (!ok) sacc[j][q] = NEGF;
            }
        }

        // ---- online softmax (in-range only) ----
        float mx0 = -3.0e38f, mx1 = -3.0e38f;
#pragma unroll
        for (int j = 0; j < 16; j++) {
            if (j < 2 * jlo || j >= 2 * jhi) continue;
            mx0 = fmaxf(mx0, fmaxf(sacc[j][0], sacc[j][1]));
            mx1 = fmaxf(mx1, fmaxf(sacc[j][2], sacc[j][3]));
        }
        mx0 = fmaxf(mx0, __shfl_xor_sync(0xffffffff, mx0, 1));
        mx0 = fmaxf(mx0, __shfl_xor_sync(0xffffffff, mx0, 2));
        mx1 = fmaxf(mx1, __shfl_xor_sync(0xffffffff, mx1, 1));
        mx1 = fmaxf(mx1, __shfl_xor_sync(0xffffffff, mx1, 2));
        float mn0 = fmaxf(m0, mx0), mn1 = fmaxf(m1, mx1);
        float f0 = __expf(m0 - mn0), f1 = __expf(m1 - mn1);
        float s0 = 0.f, s1 = 0.f;
#pragma unroll
        for (int j = 0; j < 16; j++) {
            if (j < 2 * jlo || j >= 2 * jhi) continue;
            float p0v = __expf(sacc[j][0] - mn0);
            float p1v = __expf(sacc[j][1] - mn0);
            float p2v = __expf(sacc[j][2] - mn1);
            float p3v = __expf(sacc[j][3] - mn1);
            sacc[j][0] = p0v; sacc[j][1] = p1v; sacc[j][2] = p2v; sacc[j][3] = p3v;
            s0 += p0v + p1v; s1 += p2v + p3v;
        }
        s0 += __shfl_xor_sync(0xffffffff, s0, 1);
        s0 += __shfl_xor_sync(0xffffffff, s0, 2);
        s1 += __shfl_xor_sync(0xffffffff, s1, 1);
        s1 += __shfl_xor_sync(0xffffffff, s1, 2);
        l0 = l0 * f0 + s0; l1 = l1 * f1 + s1;
        m0 = mn0; m1 = mn1;
#pragma unroll
        for (int j = 0; j < 8; j++) {
            O[j][0] *= f0; O[j][1] *= f0; O[j][2] *= f1; O[j][3] *= f1;
        }

        // ---- O += P.V over [jlo, jhi) key groups ----
#pragma unroll
        for (int ks = 0; ks < 8; ks++) {
            if (ks < jlo || ks >= jhi) continue;
            uint32_t pa[4];
            pa[0] = pack_h2(sacc[2 * ks][0],     sacc[2 * ks][1]);
            pa[1] = pack_h2(sacc[2 * ks][2],     sacc[2 * ks][3]);
            pa[2] = pack_h2(sacc[2 * ks + 1][0], sacc[2 * ks + 1][1]);
            pa[3] = pack_h2(sacc[2 * ks + 1][2], sacc[2 * ks + 1][3]);
#pragma unroll
            for (int jd = 0; jd < 4; jd++) {
                uint32_t vh4[4];
                uint32_t vb = (uint32_t)(16 * ks + tkrow) * 128 +
                              (((uint32_t)(jd * 2 + tdu) ^ (uint32_t)(lane & 7)) << 4);
                ldsm4t(vh4, sb + LA_V + vb);
                mma16816(O[2 * jd],     pa, vh4[0], vh4[1]);
                mma16816(O[2 * jd + 1], pa, vh4[2], vh4[3]);
            }
        }
    }

    float inv0 = 1.0f / l0, inv1 = 1.0f / l1;
    int s0r = qbase + qr + g;
    int s1r = s0r + 8;
    size_t b0 = ((size_t)b * Ss + s0r) * Dd + h * DHd;
    size_t b1 = ((size_t)b * Ss + s1r) * Dd + h * DHd;
#pragma unroll
    for (int jd = 0; jd < 8; jd++) {
        int cc = 8 * jd + t4 * 2;
        *(uint32_t*)(g_a + b0 + cc) = pack_h2(O[jd][0] * inv0, O[jd][1] * inv0);
        *(uint32_t*)(g_a + b1 + cc) = pack_h2(O[jd][2] * inv1, O[jd][3] * inv1);
    }
}

// ---------------- qg projection ----------------
__global__ __launch_bounds__(256) void qg_proj(const float* __restrict__ x,
                                               const float* __restrict__ Wqg,
                                               const float* __restrict__ bqg)
{
    __shared__ float xr[768];
    __shared__ float sred[256];
    int bg = blockIdx.x, cc = blockIdx.y;
    int b = bg >> 4, g = bg & 15;
    int tid = threadIdx.x;
    for (int i = tid; i < 768; i += 256) xr[i] = x[((size_t)b * Ss + g) * Dd + i];
    __syncthreads();
    int col = cc * 32 + (tid & 31);
    int ks = tid >> 5;
    int k0 = ks * 96;
    float acc = 0.f;
#pragma unroll 8
    for (int k = 0; k < 96; k++)
        acc += xr[k0 + k] * Wqg[(size_t)(k0 + k) * 768 + col];
    sred[tid] = acc;
    __syncthreads();
    if (tid < 32) {
        float tot = 0.f;
#pragma unroll
        for (int j = 0; j < 8; j++) tot += sred[tid + 32 * j];
        int c = cc * 32 + tid;
        float vv = (tot + bqg[c]) * 0.125f;
        g_qg[(((size_t)b * Hh + (c >> 6)) * Gg + g) * DHd + (c & 63)] = vv;
    }
}

// ---------------- global-row attention: 32-way split ----------------
__global__ __launch_bounds__(256) void gattn_part(const int* __restrict__ mask)
{
    extern __shared__ float sm[];
    float* Qgs  = sm;
    float* Kts  = Qgs + 16 * 68;
    float* Vs   = Kts + 64 * 132;
    float* Ps   = Vs + 128 * 68;
    float* rowm = Ps + 16 * 129;
    float* rowl = rowm + 16;

    int si = blockIdx.x, h = blockIdx.y, b = blockIdx.z;
    int tid = threadIdx.x;
    const float* kgb = g_kg + ((size_t)(b * Hh + h)) * Ss * DHd;
    const float* vgb = g_vg + ((size_t)(b * Hh + h)) * Ss * DHd;
    const int* mk = mask + b * Ss;

    for (int i = tid; i < 16 * 64; i += 256) {
        int r = i >> 6, d = i & 63;
        Qgs[r * 68 + d] = g_qg[(((size_t)b * Hh + h) * Gg + r) * DHd + d];
    }

    int p0 = si * 128;
    int r = tid >> 4, cg = tid & 15;
#pragma unroll
    for (int it = 0; it < 8; it++) {
        int idx = tid + it * 256;
        int j = idx >> 4, cv = idx & 15;
        int p = p0 + j;
        float4 kv = *(const float4*)(kgb + (size_t)p * 64 + cv * 4);
        float4 vv = *(const float4*)(vgb + (size_t)p * 64 + cv * 4);
        Kts[(cv * 4 + 0) * 132 + j] = kv.x;
        Kts[(cv * 4 + 1) * 132 + j] = kv.y;
        Kts[(cv * 4 + 2) * 132 + j] = kv.z;
        Kts[(cv * 4 + 3) * 132 + j] = kv.w;
        *(float4*)&Vs[j * 68 + cv * 4] = vv;
    }
    __syncthreads();

    float sc8[8] = {0.f, 0.f, 0.f, 0.f, 0.f, 0.f, 0.f, 0.f};
#pragma unroll 8
    for (int d = 0; d < 64; d++) {
        float a = Qgs[r * 68 + d];
#pragma unroll
        for (int j = 0; j < 8; j++) sc8[j] += a * Kts[d * 132 + cg * 8 + j];
    }
#pragma unroll
    for (int j = 0; j < 8; j++) {
        int p = p0 + cg * 8 + j;
        Ps[r * 129 + cg * 8 + j] = (mk[p] > 0) ? sc8[j] : NEGF;
    }
    __syncthreads();

    if (tid < 16) {
        float cm = -3.0e38f;
        for (int j2 = 0; j2 < 128; j2++) cm = fmaxf(cm, Ps[tid * 129 + j2]);
        float ls = 0.f;
        for (int j2 = 0; j2 < 128; j2++) {
            float pv = __expf(Ps[tid * 129 + j2] - cm);
            Ps[tid * 129 + j2] = pv;
            ls += pv;
        }
        rowm[tid] = cm;
        rowl[tid] = ls;
    }
    __syncthreads();

    float oacc[4] = {0.f, 0.f, 0.f, 0.f};
    for (int kk = 0; kk < 128; kk++) {
        float a = Ps[r * 129 + kk];
#pragma unroll
        for (int j = 0; j < 4; j++) oacc[j] += a * Vs[kk * 68 + cg * 4 + j];
    }
    int part = (b * Hh + h) * NSPLIT + si;
#pragma unroll
    for (int j = 0; j < 4; j++)
        g_pacc[((size_t)part * 16 + r) * 64 + cg * 4 + j] = oacc[j];
    if (cg == 0) {
        g_pm[part * 16 + r] = rowm[r];
        g_pl[part * 16 + r] = rowl[r];
    }
}

__global__ __launch_bounds__(32) void gattn_combine()
{
    int bh = blockIdx.x;
    int b = bh / Hh, h = bh % Hh;
    int t = threadIdx.x;
    for (int r = 0; r < Gg; r++) {
        float M = -3.0e38f;
        for (int si = 0; si < NSPLIT; si++)
            M = fmaxf(M, g_pm[((b * Hh + h) * NSPLIT + si) * 16 + r]);
        float L = 0.f, a0 = 0.f, a1 = 0.f;
        for (int si = 0; si < NSPLIT; si++) {
            int part = (b * Hh + h) * NSPLIT + si;
            float w = __expf(g_pm[part * 16 + r] - M);
            L += w * g_pl[part * 16 + r];
            a0 += w * g_pacc[((size_t)part * 16 + r) * 64 + 2 * t];
            a1 += w * g_pacc[((size_t)part * 16 + r) * 64 + 2 * t + 1];
        }
        size_t base = ((size_t)b * Ss + r) * Dd + h * DHd + 2 * t;
        *(uint32_t*)(g_a + base) = pack_h2(a0 / L, a1 / L);
    }
}

// ---------------- launch ----------------
extern "C" void kernel_launch(void* const* d_in, const int* in_sizes, int n_in,
                              void* d_out, int out_size)
{
    (void)in_sizes; (void)n_in; (void)out_size;
    const float* x    = (const float*)d_in[0];
    const int*   mask = (const int*)d_in[1];
    W6 w6;
    w6.w[0] = (const float*)d_in[2];
    w6.w[1] = (const float*)d_in[4];
    w6.w[2] = (const float*)d_in[6];
    w6.w[3] = (const float*)d_in[10];
    w6.w[4] = (const float*)d_in[12];
    w6.w[5] = (const float*)d_in[14];
    Bia5 b5;
    b5.b[0] = (const float*)d_in[3];
    b5.b[1] = (const float*)d_in[5];
    b5.b[2] = (const float*)d_in[7];
    b5.b[3] = (const float*)d_in[11];
    b5.b[4] = (const float*)d_in[13];
    const float* Wqg = (const float*)d_in[8];
    const float* bqg = (const float*)d_in[9];
    const float* bo  = (const float*)d_in[15];
    float* out = (float*)d_out;

    int gsm = (16 * 68 + 64 * 132 + 128 * 68 + 16 * 129 + 2 * 16) * 4;
    cudaFuncSetAttribute(gattn_part, cudaFuncAttributeMaxDynamicSharedMemorySize, gsm);
    cudaFuncSetAttribute(mma_gemm<false>, cudaFuncAttributeMaxDynamicSharedMemorySize, GEMM_SMEM);
    cudaFuncSetAttribute(mma_gemm<true>,  cudaFuncAttributeMaxDynamicSharedMemorySize, GEMM_SMEM);
    cudaFuncSetAttribute(local_attn, cudaFuncAttributeMaxDynamicSharedMemorySize, LA_SMEM);

    __half *xf, *af;
    cudaGetSymbolAddress((void**)&xf, g_x);
    cudaGetSymbolAddress((void**)&af, g_a);

    int n4 = Bb * Ss * Dd / 4;
    to_f16<<<(n4 + 255) / 256, 256>>>(x, xf, n4);                          // 1
    prep_w<<<dim3(24, 24, 6), dim3(32, 8)>>>(w6);                          // 2
    mma_gemm<false><<<dim3(3, 128, 5), 256, GEMM_SMEM>>>(xf, b5, nullptr, nullptr); // 3
    local_attn<<<dim3(NBb * 2, Hh, Bb), 128, LA_SMEM>>>(mask);             // 4 (profiled)
    qg_proj<<<dim3(Bb * Gg, 24), 256>>>(x, Wqg, bqg);                      // 5
    gattn_part<<<dim3(NSPLIT, Hh, Bb), 256, gsm>>>(mask);                  // 6
    gattn_combine<<<Bb * Hh, 32>>>();                                      // 7
    mma_gemm<true><<<dim3(3, 128), 256, GEMM_SMEM>>>(af, b5, bo, out);     // 8
}